// round 17
// baseline (speedup 1.0000x reference)
#include <cuda_runtime.h>

#define NN 25000
#define NE 400000
#define NTILE 3125
#define PGRID 444

#define INV_SQRT3 0.57735026919f
#define INV_SQRT2 0.70710678119f

// ---------------- scratch (device globals; allocation-free) ----------------
__device__ float4 d_g_s  [NN * 16];   // s   = s_in @ W1_0 /8           (N,64)
__device__ float4 d_g_v  [NN * 24];   // v   = v_in . W1_1 /sqrt32      (N,32,3) [u*3+c]
__device__ float4 d_g_scs[NN * 16];   // sc_s                           (N,64)
__device__ float4 d_g_scv[NN * 24];   // sc_v                           (N,96)  [u*3+c]
__device__ float4 d_g_ns [NN * 24];   // scatter accum s-part           (N,96)
__device__ float4 d_g_nv [NN * 96];   // scatter accum v-part           (N,3,128) [c][u]
__device__ float  d_W1K[8 * 64];      // Wfc1 natural [k][j], prescaled 1/sqrt(8)
__device__ float  d_W2K[64 * 64];     // Wfc2 natural [k][j], prescaled 1/8
// Wfc3 PERMUTED layout [k][R], prescaled (see R14 mapping).
__device__ float  d_W3K[64 * 256];

// ---------------- f32x2 / async helpers ----------------
#define FMA2(d, a, b) \
    asm("fma.rn.f32x2 %0, %1, %2, %0;" : "+l"(d) : "l"(a), "l"(b))
#define PACK2(d, lo, hi) \
    asm("mov.b64 %0, {%1, %2};" : "=l"(d) : "f"(lo), "f"(hi))
#define UNPACK2(lo, hi, s) \
    asm("mov.b64 {%0, %1}, %2;" : "=f"(lo), "=f"(hi) : "l"(s))

__device__ __forceinline__ void cpa16(unsigned int saddr, const float* g) {
    asm volatile("cp.async.ca.shared.global [%0], [%1], 16;"
                 :: "r"(saddr), "l"(g) : "memory");
}
#define CP_COMMIT() asm volatile("cp.async.commit_group;" ::: "memory")
#define CP_WAIT(n)  asm volatile("cp.async.wait_group %0;" :: "n"(n) : "memory")

__device__ __forceinline__ float silu_f(float x) {
    return x / (1.0f + __expf(-x));
}

__device__ __forceinline__ void red4(float* p, float a, float b, float c, float d) {
    asm volatile("red.global.add.v4.f32 [%0], {%1,%2,%3,%4};"
                 :: "l"(p), "f"(a), "f"(b), "f"(c), "f"(d) : "memory");
}

// ---------------- 8x8 register-tiled GEMM (acc stays in registers) ---------
template <int KLEN>
__device__ __forceinline__ void gemm_acc(const float* __restrict__ sAm,
                                         const float* __restrict__ sBm,
                                         unsigned long long* acc,
                                         int jt, int et) {
    const float* Ap = sAm + jt * 8;
    const float* Bp = sBm + et * 8;
#pragma unroll
    for (int i = 0; i < 32; ++i) acc[i] = 0ull;
#pragma unroll 4
    for (int k = 0; k < KLEN; ++k) {
        float4 a0 = *reinterpret_cast<const float4*>(Ap + k * 64);
        float4 a1 = *reinterpret_cast<const float4*>(Ap + k * 64 + 4);
        ulonglong2 b01 = *reinterpret_cast<const ulonglong2*>(Bp + k * 128);
        ulonglong2 b23 = *reinterpret_cast<const ulonglong2*>(Bp + k * 128 + 4);
        unsigned long long ap;
        PACK2(ap, a0.x, a0.x);
        FMA2(acc[0],  ap, b01.x); FMA2(acc[1],  ap, b01.y);
        FMA2(acc[2],  ap, b23.x); FMA2(acc[3],  ap, b23.y);
        PACK2(ap, a0.y, a0.y);
        FMA2(acc[4],  ap, b01.x); FMA2(acc[5],  ap, b01.y);
        FMA2(acc[6],  ap, b23.x); FMA2(acc[7],  ap, b23.y);
        PACK2(ap, a0.z, a0.z);
        FMA2(acc[8],  ap, b01.x); FMA2(acc[9],  ap, b01.y);
        FMA2(acc[10], ap, b23.x); FMA2(acc[11], ap, b23.y);
        PACK2(ap, a0.w, a0.w);
        FMA2(acc[12], ap, b01.x); FMA2(acc[13], ap, b01.y);
        FMA2(acc[14], ap, b23.x); FMA2(acc[15], ap, b23.y);
        PACK2(ap, a1.x, a1.x);
        FMA2(acc[16], ap, b01.x); FMA2(acc[17], ap, b01.y);
        FMA2(acc[18], ap, b23.x); FMA2(acc[19], ap, b23.y);
        PACK2(ap, a1.y, a1.y);
        FMA2(acc[20], ap, b01.x); FMA2(acc[21], ap, b01.y);
        FMA2(acc[22], ap, b23.x); FMA2(acc[23], ap, b23.y);
        PACK2(ap, a1.z, a1.z);
        FMA2(acc[24], ap, b01.x); FMA2(acc[25], ap, b01.y);
        FMA2(acc[26], ap, b23.x); FMA2(acc[27], ap, b23.y);
        PACK2(ap, a1.w, a1.w);
        FMA2(acc[28], ap, b01.x); FMA2(acc[29], ap, b01.y);
        FMA2(acc[30], ap, b23.x); FMA2(acc[31], ap, b23.y);
    }
}

// 4x8 tile for the 32-row chunk3 (A stride 32)
template <int KLEN>
__device__ __forceinline__ void gemm_acc4(const float* __restrict__ sAm,
                                          const float* __restrict__ sBm,
                                          unsigned long long* acc,
                                          int jt, int et) {
    const float* Ap = sAm + jt * 4;
    const float* Bp = sBm + et * 8;
#pragma unroll
    for (int i = 0; i < 16; ++i) acc[i] = 0ull;
#pragma unroll 4
    for (int k = 0; k < KLEN; ++k) {
        float4 a0 = *reinterpret_cast<const float4*>(Ap + k * 32);
        ulonglong2 b01 = *reinterpret_cast<const ulonglong2*>(Bp + k * 128);
        ulonglong2 b23 = *reinterpret_cast<const ulonglong2*>(Bp + k * 128 + 4);
        unsigned long long ap;
        PACK2(ap, a0.x, a0.x);
        FMA2(acc[0],  ap, b01.x); FMA2(acc[1],  ap, b01.y);
        FMA2(acc[2],  ap, b23.x); FMA2(acc[3],  ap, b23.y);
        PACK2(ap, a0.y, a0.y);
        FMA2(acc[4],  ap, b01.x); FMA2(acc[5],  ap, b01.y);
        FMA2(acc[6],  ap, b23.x); FMA2(acc[7],  ap, b23.y);
        PACK2(ap, a0.z, a0.z);
        FMA2(acc[8],  ap, b01.x); FMA2(acc[9],  ap, b01.y);
        FMA2(acc[10], ap, b23.x); FMA2(acc[11], ap, b23.y);
        PACK2(ap, a0.w, a0.w);
        FMA2(acc[12], ap, b01.x); FMA2(acc[13], ap, b01.y);
        FMA2(acc[14], ap, b23.x); FMA2(acc[15], ap, b23.y);
    }
}

// store acc with silu into sD (stride 128)
__device__ __forceinline__ void store_silu(const unsigned long long* acc,
                                           float* __restrict__ sD,
                                           int jt, int et) {
    float* D = sD + (size_t)(jt * 8) * 128 + et * 8;
#pragma unroll
    for (int j = 0; j < 8; ++j) {
#pragma unroll
        for (int i = 0; i < 4; ++i) {
            float lo, hi;
            UNPACK2(lo, hi, acc[j * 4 + i]);
            unsigned long long p;
            PACK2(p, silu_f(lo), silu_f(hi));
            *reinterpret_cast<unsigned long long*>(D + j * 128 + 2 * i) = p;
        }
    }
}

// ---------------- consume helpers (edge data from smem cache) --------------
__device__ __forceinline__ void cons_A(const float* w, int el, int j0,
                                       const int* sSrc, const int* sDst,
                                       const float4* sSh) {
    int src = sSrc[el], dst = sDst[el];
    float4 sh = sSh[el];
    float4 s = __ldg(reinterpret_cast<const float4*>(
        (const float*)d_g_s + (size_t)dst * 64 + j0));
    float* nsp = (float*)d_g_ns + (size_t)src * 96 + j0;
    red4(nsp, w[0]*s.x*sh.x, w[1]*s.y*sh.x, w[2]*s.z*sh.x, w[3]*s.w*sh.x);
    float a0 = w[4]*s.x, a1 = w[5]*s.y, a2 = w[6]*s.z, a3 = w[7]*s.w;
    float* nvp = (float*)d_g_nv + (size_t)src * 384 + j0;
    red4(nvp,       a0*sh.y, a1*sh.y, a2*sh.y, a3*sh.y);
    red4(nvp + 128, a0*sh.z, a1*sh.z, a2*sh.z, a3*sh.z);
    red4(nvp + 256, a0*sh.w, a1*sh.w, a2*sh.w, a3*sh.w);
}

__device__ __forceinline__ void cons_B(const float* w, int el, int u0,
                                       const int* sSrc, const int* sDst,
                                       const float4* sSh) {
    int src = sSrc[el], dst = sDst[el];
    float4 sh = sSh[el];
    const float4* vp = reinterpret_cast<const float4*>(
        (const float*)d_g_v + (size_t)dst * 96 + u0 * 3);
    float4 v0 = __ldg(vp), v1 = __ldg(vp + 1), v2 = __ldg(vp + 2);
    float vv[12] = {v0.x,v0.y,v0.z,v0.w, v1.x,v1.y,v1.z,v1.w,
                    v2.x,v2.y,v2.z,v2.w};
    float* nvp = (float*)d_g_nv + (size_t)src * 384;
#pragma unroll
    for (int c = 0; c < 3; ++c) {
        red4(nvp + c*128 + 64 + u0,
             w[0]*vv[0+c]*sh.x, w[1]*vv[3+c]*sh.x,
             w[2]*vv[6+c]*sh.x, w[3]*vv[9+c]*sh.x);
    }
    float m[4];
#pragma unroll
    for (int q = 0; q < 4; ++q)
        m[q] = w[4+q] * (vv[q*3]*sh.y + vv[q*3+1]*sh.z + vv[q*3+2]*sh.w);
    red4((float*)d_g_ns + (size_t)src * 96 + 64 + u0, m[0], m[1], m[2], m[3]);
}

__device__ __forceinline__ void cons_C(const float* w, int el, int u0,
                                       const int* sSrc, const int* sDst,
                                       const float4* sSh) {
    int src = sSrc[el], dst = sDst[el];
    float4 sh = sSh[el];
    const float4* vp = reinterpret_cast<const float4*>(
        (const float*)d_g_v + (size_t)dst * 96 + u0 * 3);
    float4 v0 = __ldg(vp), v1 = __ldg(vp + 1), v2 = __ldg(vp + 2);
    float vv[12] = {v0.x,v0.y,v0.z,v0.w, v1.x,v1.y,v1.z,v1.w,
                    v2.x,v2.y,v2.z,v2.w};
    float mx[4], my[4], mz[4];
#pragma unroll
    for (int q = 0; q < 4; ++q) {
        float vx = vv[q*3], vy = vv[q*3+1], vz = vv[q*3+2];
        mx[q] = w[q] * (vy*sh.w - vz*sh.z);
        my[q] = w[q] * (vz*sh.y - vx*sh.w);
        mz[q] = w[q] * (vx*sh.z - vy*sh.y);
    }
    float* nvp = (float*)d_g_nv + (size_t)src * 384;
    red4(nvp +       96 + u0, mx[0], mx[1], mx[2], mx[3]);
    red4(nvp + 128 + 96 + u0, my[0], my[1], my[2], my[3]);
    red4(nvp + 256 + 96 + u0, mz[0], mz[1], mz[2], mz[3]);
}

// ---------------- kernel 1: init (zero + prescale/permute + node prep) ------
__global__ void __launch_bounds__(256) k_init(const float* __restrict__ nh,
                                              const float* __restrict__ W1_0,
                                              const float* __restrict__ W1_1,
                                              const float* __restrict__ Wsc0,
                                              const float* __restrict__ Wsc1,
                                              const float* __restrict__ Wfc1,
                                              const float* __restrict__ Wfc2,
                                              const float* __restrict__ Wfc3) {
    extern __shared__ float smi[];
    float* sW10  = smi;            // 4096
    float* sWsc0 = smi + 4096;     // 4096
    float* sW11  = smi + 8192;     // 1024
    float* sWsc1 = smi + 9216;     // 1024
    float* sStg  = smi + 10240;    // 8 warps * 800
    int t = threadIdx.x;
    int gid = blockIdx.x * 256 + t;
    const int GSTRIDE = 391 * 256;

    // --- grid-strided: zero accumulators (3M float4) ---
    {
        float4 z = make_float4(0.f, 0.f, 0.f, 0.f);
        for (int i = gid; i < NN * 120; i += GSTRIDE) {
            if (i < NN * 24) d_g_ns[i] = z;
            else             d_g_nv[i - NN * 24] = z;
        }
    }
    // --- grid-strided: weight prescale + W3 permute (20992 entries) ---
    for (int j = gid; j < 20992; j += GSTRIDE) {
        if (j < 512) {
            d_W1K[j] = Wfc1[j] * 0.3535533906f;
        } else if (j < 4608) {
            d_W2K[j - 512] = Wfc2[j - 512] * 0.125f;
        } else {
            int m = j - 4608;
            int k = m >> 8, R = m & 255;
            int orig = -1;
            if (R < 192) {
                int chunk = R >> 6, r = R & 63, jtp = r >> 3, q = r & 7;
                int fh, sh2;
                if (chunk == 0)      { fh = 0;   sh2 = 64;  }
                else if (chunk == 1) { fh = 32;  sh2 = 96;  }
                else                 { fh = 128; sh2 = 160; }
                orig = (q < 4) ? (fh + jtp * 4 + q) : (sh2 + jtp * 4 + q - 4);
            } else if (R < 224) {
                orig = R;   // w4 rows, identity
            }
            float v = 0.f;
            if (orig >= 0) {
                float s = 0.03125f;  // (1/sqrt(64)) * (1/sqrt(16))
                if (orig >= 192)      s *= INV_SQRT2;
                else if (orig >= 160) s *= INV_SQRT3;
                v = Wfc3[k * 224 + orig] * s;
            }
            d_W3K[m] = v;
        }
    }

    // --- load weights to smem ---
    for (int i = t; i < 4096; i += 256) { sW10[i] = W1_0[i]; sWsc0[i] = Wsc0[i]; }
    for (int i = t; i < 1024; i += 256) { sW11[i] = W1_1[i]; sWsc1[i] = Wsc1[i]; }
    __syncthreads();

    int wid = t >> 5, l = t & 31;
    float* gs  = (float*)d_g_s;
    float* gv  = (float*)d_g_v;
    float* gss = (float*)d_g_scs;
    float* gsv = (float*)d_g_scv;
    float* buf = sStg + wid * 800;   // buf[i*5 + j], i < 160, j < 4

    for (int it = 0; it < 2; ++it) {
        int nb = blockIdx.x * 64 + it * 32 + wid * 4;

        // stage 4 nodes' inputs (stride-5: conflict-free STS, broadcast reads)
#pragma unroll
        for (int j = 0; j < 4; ++j) {
            int nj = min(nb + j, NN - 1);
            const float* src = nh + (size_t)nj * 160;
#pragma unroll
            for (int m = 0; m < 5; ++m) {
                int i = l + 32 * m;
                buf[i * 5 + j] = __ldg(src + i);
            }
        }
        __syncwarp();

        // ---- s part: outputs o = l and o = l+32 for 4 nodes ----
        float a0[4] = {0,0,0,0}, a1[4] = {0,0,0,0};
        float b0[4] = {0,0,0,0}, b1[4] = {0,0,0,0};
#pragma unroll 4
        for (int u = 0; u < 64; ++u) {
            float w0  = sW10 [u * 64 + l];
            float w1  = sW10 [u * 64 + l + 32];
            float ws0 = sWsc0[u * 64 + l];
            float ws1 = sWsc0[u * 64 + l + 32];
#pragma unroll
            for (int j = 0; j < 4; ++j) {
                float x = buf[u * 5 + j];
                a0[j] += x * w0;  a1[j] += x * w1;
                b0[j] += x * ws0; b1[j] += x * ws1;
            }
        }
#pragma unroll
        for (int j = 0; j < 4; ++j) {
            int n = nb + j;
            if (n < NN) {
                gs [(size_t)n * 64 + l]      = a0[j] * 0.125f;
                gs [(size_t)n * 64 + l + 32] = a1[j] * 0.125f;
                gss[(size_t)n * 64 + l]      = b0[j] * 0.125f;
                gss[(size_t)n * 64 + l + 32] = b1[j] * 0.125f;
            }
        }

        // ---- v part: lane l = output row u'=l, components c=0..2 ----
        float va[3][4], vb[3][4];
#pragma unroll
        for (int c = 0; c < 3; ++c)
#pragma unroll
            for (int j = 0; j < 4; ++j) { va[c][j] = 0.f; vb[c][j] = 0.f; }
#pragma unroll 4
        for (int u = 0; u < 32; ++u) {
            float wv  = sW11 [u * 32 + l];
            float wsv = sWsc1[u * 32 + l];
#pragma unroll
            for (int c = 0; c < 3; ++c) {
#pragma unroll
                for (int j = 0; j < 4; ++j) {
                    float x = buf[(64 + u * 3 + c) * 5 + j];
                    va[c][j] += x * wv;
                    vb[c][j] += x * wsv;
                }
            }
        }
#pragma unroll
        for (int j = 0; j < 4; ++j) {
            int n = nb + j;
            if (n < NN) {
#pragma unroll
                for (int c = 0; c < 3; ++c) {
                    gv [(size_t)n * 96 + 3 * l + c] = va[c][j] * 0.1767766953f;
                    gsv[(size_t)n * 96 + 3 * l + c] = vb[c][j] * 0.1767766953f;
                }
            }
        }
        __syncwarp();
    }
}

// ---------------- kernel 3: persistent fused GEMM + register consume -------
// 444 blocks; each loops over tiles (bid, bid+444, ...). Per-tile body is
// identical to R16. Top-of-tile barrier protects sB/buf1/caches reuse.
__global__ void __launch_bounds__(128, 3) k_edge(const int* __restrict__ ei,
                                                 const float* __restrict__ esh,
                                                 const float* __restrict__ eattr) {
    extern __shared__ float sm[];
    float* sB = sm + 8192;
    int* sSrc = (int*)(sm + 16384);
    int* sDst = (int*)(sm + 16512);
    float4* sSh = (float4*)(sm + 16640);
    int t = threadIdx.x;
    int jt = t & 7, et = t >> 3;
    unsigned int sA0 = (unsigned int)__cvta_generic_to_shared(sm);
    int el0 = et * 8;
    int j0 = jt * 4;

    for (int tile = blockIdx.x; tile < NTILE; tile += PGRID) {
        int ebase = tile * 128;
        __syncthreads();   // previous tile's consume done before restaging

        // stage att [k][e] into sB; edge cache; W1K into buf1
        {
            int e = ebase + t;
            const float4* ap = reinterpret_cast<const float4*>(eattr + (size_t)e * 8);
            float4 a0 = __ldg(ap), a1 = __ldg(ap + 1);
            sB[0*128+t] = a0.x; sB[1*128+t] = a0.y;
            sB[2*128+t] = a0.z; sB[3*128+t] = a0.w;
            sB[4*128+t] = a1.x; sB[5*128+t] = a1.y;
            sB[6*128+t] = a1.z; sB[7*128+t] = a1.w;
            sSrc[t] = __ldg(ei + e);
            sDst[t] = __ldg(ei + NE + e);
            sSh[t]  = __ldg(reinterpret_cast<const float4*>(esh + (size_t)e * 4));
            for (int i = t; i < 512; i += 128) sm[4096 + i] = d_W1K[i];
        }
        // prefetch W2K -> buf0
#pragma unroll
        for (int r = 0; r < 8; ++r) {
            int idx = t + 128 * r;
            cpa16(sA0 + idx * 16, d_W2K + idx * 4);
        }
        CP_COMMIT();
        __syncthreads();

        unsigned long long acc[32];

        // ---- MLP1 ----
        gemm_acc<8>(sm + 4096, sB, acc, jt, et);
        __syncthreads();
        store_silu(acc, sB, jt, et);
        // prefetch chunk0 -> buf1
#pragma unroll
        for (int r = 0; r < 8; ++r) {
            int idx4 = t + 128 * r;
            int k = idx4 >> 4;
            int jj = (idx4 & 15) * 4;
            cpa16(sA0 + 16384 + (k * 64 + jj) * 4, d_W3K + k * 256 + jj);
        }
        CP_COMMIT();
        CP_WAIT(1);
        __syncthreads();

        // ---- MLP2 ----
        gemm_acc<64>(sm, sB, acc, jt, et);
        __syncthreads();
        store_silu(acc, sB, jt, et);

        // ---- 4 chunks ----
#pragma unroll 1
        for (int c = 0; c < 4; ++c) {
            CP_WAIT(0);
            __syncthreads();
            const float* bufc = sm + ((c & 1) ? 0 : 4096);
            if (c < 3) gemm_acc<64>(bufc, sB, acc, jt, et);
            else       gemm_acc4<64>(bufc, sB, acc, jt, et);

            if (c < 2) {
                unsigned int dstoff = (c & 1) ? 16384u : 0u;
#pragma unroll
                for (int r = 0; r < 8; ++r) {
                    int idx4 = t + 128 * r;
                    int k = idx4 >> 4;
                    int jj = (idx4 & 15) * 4;
                    cpa16(sA0 + dstoff + (k * 64 + jj) * 4,
                          d_W3K + k * 256 + 64 * (c + 1) + jj);
                }
                CP_COMMIT();
            } else if (c == 2) {
#pragma unroll
                for (int r = 0; r < 4; ++r) {
                    int idx4 = t + 128 * r;
                    int k = idx4 >> 3;
                    int jj = (idx4 & 7) * 4;
                    cpa16(sA0 + (k * 32 + jj) * 4, d_W3K + k * 256 + 192 + jj);
                }
                CP_COMMIT();
            }

#pragma unroll
            for (int i = 0; i < 4; ++i) {
                float wa[8], wb[8];
                if (c < 3) {
#pragma unroll
                    for (int j = 0; j < 8; ++j) UNPACK2(wa[j], wb[j], acc[j * 4 + i]);
                } else {
#pragma unroll
                    for (int j = 0; j < 4; ++j) UNPACK2(wa[j], wb[j], acc[j * 4 + i]);
                }
                int ea = el0 + 2 * i, eb = ea + 1;
                if (c == 0) {
                    cons_A(wa, ea, j0, sSrc, sDst, sSh);
                    cons_A(wb, eb, j0, sSrc, sDst, sSh);
                } else if (c == 1) {
                    cons_A(wa, ea, j0 + 32, sSrc, sDst, sSh);
                    cons_A(wb, eb, j0 + 32, sSrc, sDst, sSh);
                } else if (c == 2) {
                    cons_B(wa, ea, j0, sSrc, sDst, sSh);
                    cons_B(wb, eb, j0, sSrc, sDst, sSh);
                } else {
                    cons_C(wa, ea, j0, sSrc, sDst, sSh);
                    cons_C(wb, eb, j0, sSrc, sDst, sSh);
                }
            }
        }
    }
}

// ---------------- kernel 4: output projection + skip + RMS, 4 nodes/warp ----
__global__ void __launch_bounds__(256) k_out(float* __restrict__ out,
                                             const float* __restrict__ W2_0,
                                             const float* __restrict__ W2_1,
                                             const float* __restrict__ g0,
                                             const float* __restrict__ g1) {
    extern __shared__ float smo[];
    float* sW20 = smo;           // 6144
    float* sW21 = smo + 6144;    // 4096
    float* sG   = smo + 10240;   // 96 (+32 pad)
    float* sBuf = smo + 10368;   // 8 warps * 640
    int t = threadIdx.x;
    for (int i = t; i < 6144; i += 256) sW20[i] = W2_0[i];
    for (int i = t; i < 4096; i += 256) sW21[i] = W2_1[i];
    if (t < 64) sG[t] = g0[t];
    else if (t < 96) sG[t] = g1[t - 64];
    __syncthreads();

    const float* gnsF = (const float*)d_g_ns;
    const float* gnvF = (const float*)d_g_nv;
    const float* gssF = (const float*)d_g_scs;
    const float* gsvF = (const float*)d_g_scv;

    int wid = t >> 5, l = t & 31;
    float* buf = sBuf + wid * 640;     // buf[k*5 + j]

    for (int it = 0; it < 2; ++it) {
        int nb = blockIdx.x * 64 + it * 32 + wid * 4;

        // ======== s section ========
#pragma unroll
        for (int j = 0; j < 4; ++j) {
            int nj = min(nb + j, NN - 1);
#pragma unroll
            for (int m = 0; m < 3; ++m) {
                int k = l + 32 * m;
                buf[k * 5 + j] = __ldg(gnsF + (size_t)nj * 96 + k);
            }
        }
        __syncwarp();

        float as0[4] = {0.f, 0.f, 0.f, 0.f};
        float as1[4] = {0.f, 0.f, 0.f, 0.f};
#pragma unroll 4
        for (int k = 0; k < 96; ++k) {
            float w0 = sW20[k * 64 + l];
            float w1 = sW20[k * 64 + l + 32];
            float a0 = buf[k * 5 + 0], a1 = buf[k * 5 + 1];
            float a2 = buf[k * 5 + 2], a3 = buf[k * 5 + 3];
            as0[0] += a0 * w0; as0[1] += a1 * w0; as0[2] += a2 * w0; as0[3] += a3 * w0;
            as1[0] += a0 * w1; as1[1] += a1 * w1; as1[2] += a2 * w1; as1[3] += a3 * w1;
        }
        __syncwarp();

        float vs0[4], vs1[4], ssq_s[4];
#pragma unroll
        for (int j = 0; j < 4; ++j) {
            int nj = min(nb + j, NN - 1);
            float v0 = as0[j] * 0.1020620726f + __ldg(gssF + (size_t)nj * 64 + l);
            float v1 = as1[j] * 0.1020620726f + __ldg(gssF + (size_t)nj * 64 + l + 32);
            vs0[j] = v0; vs1[j] = v1;
            ssq_s[j] = v0 * v0 + v1 * v1;
        }

        // ======== v sections ========
        float vvs[3][4];
        float ssq_v[4] = {0.f, 0.f, 0.f, 0.f};
#pragma unroll 1
        for (int c = 0; c < 3; ++c) {
#pragma unroll
            for (int j = 0; j < 4; ++j) {
                int nj = min(nb + j, NN - 1);
#pragma unroll
                for (int m = 0; m < 4; ++m) {
                    int u = l + 32 * m;
                    buf[u * 5 + j] = __ldg(gnvF + (size_t)nj * 384 + c * 128 + u);
                }
            }
            __syncwarp();

            float av[4] = {0.f, 0.f, 0.f, 0.f};
#pragma unroll 4
            for (int u = 0; u < 128; ++u) {
                float w = sW21[u * 32 + l];
                av[0] += buf[u * 5 + 0] * w;
                av[1] += buf[u * 5 + 1] * w;
                av[2] += buf[u * 5 + 2] * w;
                av[3] += buf[u * 5 + 3] * w;
            }
            __syncwarp();

            int o = l * 3 + c;
#pragma unroll
            for (int j = 0; j < 4; ++j) {
                int nj = min(nb + j, NN - 1);
                float val = av[j] * 0.0883883476f + __ldg(gsvF + (size_t)nj * 96 + o);
                vvs[c][j] = val;
                ssq_v[j] += val * val;
            }
        }

        // ======== warp reductions + writes ========
#pragma unroll
        for (int d = 16; d; d >>= 1) {
#pragma unroll
            for (int j = 0; j < 4; ++j) {
                ssq_s[j] += __shfl_xor_sync(0xffffffffu, ssq_s[j], d);
                ssq_v[j] += __shfl_xor_sync(0xffffffffu, ssq_v[j], d);
            }
        }
#pragma unroll
        for (int j = 0; j < 4; ++j) {
            int n = nb + j;
            if (n < NN) {
                float rs = rsqrtf(ssq_s[j] * (1.0f / 64.0f) + 1e-5f);
                float rv = rsqrtf(ssq_v[j] * (1.0f / 32.0f) + 1e-5f);
                out[(size_t)n * 160 + l]      = vs0[j] * rs * sG[l];
                out[(size_t)n * 160 + l + 32] = vs1[j] * rs * sG[l + 32];
                float gv = rv * sG[64 + l];
#pragma unroll
                for (int c = 0; c < 3; ++c)
                    out[(size_t)n * 160 + 64 + l * 3 + c] = vvs[c][j] * gv;
            }
        }
        __syncwarp();
    }
}

// ---------------- launch ----------------
extern "C" void kernel_launch(void* const* d_in, const int* in_sizes, int n_in,
                              void* d_out, int out_size) {
    const float* nh    = (const float*)d_in[0];
    const int*   ei    = (const int*)  d_in[1];
    const float* esh   = (const float*)d_in[2];
    const float* eattr = (const float*)d_in[3];
    const float* W1_0  = (const float*)d_in[4];
    const float* W1_1  = (const float*)d_in[5];
    const float* Wfc1  = (const float*)d_in[6];
    const float* Wfc2  = (const float*)d_in[7];
    const float* Wfc3  = (const float*)d_in[8];
    const float* W2_0  = (const float*)d_in[9];
    const float* W2_1  = (const float*)d_in[10];
    const float* Wsc0  = (const float*)d_in[11];
    const float* Wsc1  = (const float*)d_in[12];
    const float* g0    = (const float*)d_in[13];
    const float* g1    = (const float*)d_in[14];
    float* out = (float*)d_out;

    cudaFuncSetAttribute(k_init, cudaFuncAttributeMaxDynamicSharedMemorySize, 66560);
    cudaFuncSetAttribute(k_edge, cudaFuncAttributeMaxDynamicSharedMemorySize, 68608);
    cudaFuncSetAttribute(k_out, cudaFuncAttributeMaxDynamicSharedMemorySize, 61952);

    k_init<<<391, 256, 66560>>>(nh, W1_0, W1_1, Wsc0, Wsc1, Wfc1, Wfc2, Wfc3);
    k_edge<<<PGRID, 128, 68608>>>(ei, esh, eattr);
    k_out<<<391, 256, 61952>>>(out, W2_0, W2_1, g0, g1);
}